// round 2
// baseline (speedup 1.0000x reference)
#include <cuda_runtime.h>
#include <cuda_bf16.h>

// SSIM loss: X,Y (32,8,320,320) fp32, 7x7 uniform box (valid), out = 1 - mean(S)
// Tile: 32 (w) x 64 (h) outputs per block, one (n*c) image slice per blockIdx.z.
// Phase 1: horizontal 7-window sums of {x, y, xx, yy, xy} via register sliding,
//          written to SMEM as float4(hx,hy,hxx,hyy) + float(hxy).
// Phase 2: vertical 7-window sums via register ring buffer, SSIM math,
//          block reduce, atomicAdd(double) into a global accumulator.

#define WIN     7
#define TILE_W  32
#define TILE_H  64
#define HS_ROWS (TILE_H + WIN - 1)   // 70
#define IMG     320
#define OUT     314                  // 320 - 7 + 1
#define NIMG    256                  // 32 * 8
#define NELEM   25240576.0           // 256 * 314 * 314

__device__ double g_accum;

__global__ void ssim_init_kernel() { g_accum = 0.0; }

__global__ void ssim_final_kernel(float* out) {
    out[0] = (float)(1.0 - g_accum / NELEM);
}

__global__ __launch_bounds__(256) void ssim_main_kernel(
    const float* __restrict__ X, const float* __restrict__ Y,
    const float* __restrict__ data_range, const float* __restrict__ w)
{
    __shared__ float4 hs4[HS_ROWS][TILE_W + 1];   // hx, hy, hxx, hyy
    __shared__ float  hxy[HS_ROWS][TILE_W + 1];   // hxy
    __shared__ float  warpsum[8];

    const int img = blockIdx.z;
    const int tx0 = blockIdx.x * TILE_W;
    const int ty0 = blockIdx.y * TILE_H;
    const float* Xb = X + (size_t)img * IMG * IMG;
    const float* Yb = Y + (size_t)img * IMG * IMG;
    const int tid = threadIdx.y * 32 + threadIdx.x;

    // ---------------- Phase 1: horizontal window sums ----------------
    // 280 tasks: 70 rows x 4 chunks of 8 output columns. Each task loads
    // 14 consecutive x,y values and slides a 7-wide window across them.
    for (int t = tid; t < HS_ROWS * (TILE_W / 8); t += 256) {
        const int row = t >> 2;
        const int c0  = (t & 3) * 8;
        const int gy  = ty0 + row;
        const bool rowok = (gy < IMG);
        const float* xr = Xb + gy * IMG + tx0 + c0;
        const float* yr = Yb + gy * IMG + tx0 + c0;

        float xv[14], yv[14];
        #pragma unroll
        for (int j = 0; j < 14; j++) {
            const int gx = tx0 + c0 + j;
            const bool ok = rowok && (gx < IMG);
            xv[j] = ok ? __ldg(xr + j) : 0.0f;
            yv[j] = ok ? __ldg(yr + j) : 0.0f;
        }

        float sx = 0.f, sy = 0.f, sxx = 0.f, syy = 0.f, sxy = 0.f;
        #pragma unroll
        for (int j = 0; j < 7; j++) {
            sx += xv[j];
            sy += yv[j];
            sxx = fmaf(xv[j], xv[j], sxx);
            syy = fmaf(yv[j], yv[j], syy);
            sxy = fmaf(xv[j], yv[j], sxy);
        }
        hs4[row][c0] = make_float4(sx, sy, sxx, syy);
        hxy[row][c0] = sxy;

        #pragma unroll
        for (int j = 1; j < 8; j++) {
            const float xn = xv[j + 6], yn = yv[j + 6];
            const float xo = xv[j - 1], yo = yv[j - 1];
            sx  += xn - xo;
            sy  += yn - yo;
            sxx += xn * xn - xo * xo;
            syy += yn * yn - yo * yo;
            sxy += xn * yn - xo * yo;
            hs4[row][c0 + j] = make_float4(sx, sy, sxx, syy);
            hxy[row][c0 + j] = sxy;
        }
    }
    __syncthreads();

    // ---------------- Phase 2: vertical window sums + SSIM ----------------
    const float wscale = w[0];                 // uniform box weight (1/49)
    const float dr = data_range[0];
    const float c1t = 0.01f * dr;
    const float c2t = 0.03f * dr;
    const float C1 = c1t * c1t;
    const float C2 = c2t * c2t;
    const float COV = 49.0f / 48.0f;           // NP_WIN / (NP_WIN - 1)

    const int c  = threadIdx.x;                // output column within tile
    const int r0 = threadIdx.y * 8;            // first of 8 contiguous output rows

    float4 ring[7];
    float  ringxy[7];
    float4 s4 = make_float4(0.f, 0.f, 0.f, 0.f);
    float  sxy = 0.f;
    #pragma unroll
    for (int k = 0; k < 7; k++) {
        const float4 v = hs4[r0 + k][c];
        const float  vv = hxy[r0 + k][c];
        ring[k] = v; ringxy[k] = vv;
        s4.x += v.x; s4.y += v.y; s4.z += v.z; s4.w += v.w;
        sxy  += vv;
    }

    float local = 0.f;
    const int ox = tx0 + c;
    #pragma unroll
    for (int i = 0; i < 8; i++) {
        const int oy = ty0 + r0 + i;
        if (ox < OUT && oy < OUT) {
            const float ux  = s4.x * wscale;
            const float uy  = s4.y * wscale;
            const float uxx = s4.z * wscale;
            const float uyy = s4.w * wscale;
            const float uxy = sxy  * wscale;
            const float vx  = COV * (uxx - ux * ux);
            const float vy  = COV * (uyy - uy * uy);
            const float vxy = COV * (uxy - ux * uy);
            const float A1 = 2.0f * ux * uy + C1;
            const float A2 = 2.0f * vxy + C2;
            const float B1 = ux * ux + uy * uy + C1;
            const float B2 = vx + vy + C2;
            local += (A1 * A2) / (B1 * B2 + 1e-8f);
        }
        if (i < 7) {
            const float4 nv  = hs4[r0 + i + 7][c];
            const float  nxy = hxy[r0 + i + 7][c];
            s4.x += nv.x - ring[i].x;
            s4.y += nv.y - ring[i].y;
            s4.z += nv.z - ring[i].z;
            s4.w += nv.w - ring[i].w;
            sxy  += nxy  - ringxy[i];
        }
    }

    // ---------------- Block reduction ----------------
    #pragma unroll
    for (int off = 16; off > 0; off >>= 1)
        local += __shfl_down_sync(0xffffffffu, local, off);
    if (threadIdx.x == 0) warpsum[threadIdx.y] = local;
    __syncthreads();
    if (tid < 8) {
        float v = warpsum[tid];
        #pragma unroll
        for (int off = 4; off > 0; off >>= 1)
            v += __shfl_down_sync(0xffu, v, off);
        if (tid == 0) atomicAdd(&g_accum, (double)v);
    }
}

extern "C" void kernel_launch(void* const* d_in, const int* in_sizes, int n_in,
                              void* d_out, int out_size) {
    const float* X  = (const float*)d_in[0];
    const float* Y  = (const float*)d_in[1];
    const float* dr = (const float*)d_in[2];
    const float* w  = (const float*)d_in[3];
    float* out = (float*)d_out;

    ssim_init_kernel<<<1, 1>>>();
    dim3 grid((OUT + TILE_W - 1) / TILE_W,   // 10
              (OUT + TILE_H - 1) / TILE_H,   // 5
              NIMG);                         // 256
    dim3 block(32, 8);
    ssim_main_kernel<<<grid, block>>>(X, Y, dr, w);
    ssim_final_kernel<<<1, 1>>>(out);
}

// round 4
// speedup vs baseline: 1.7105x; 1.7105x over previous
#include <cuda_runtime.h>
#include <cuda_bf16.h>

// SSIM loss: X,Y (32,8,320,320) fp32, 7x7 uniform box (valid), out = 1 - mean(S)
//
// Separable box sums, vertical-first for coalescing:
//   Phase 1: one thread per image COLUMN (64 cols/block, lanes = consecutive
//            columns -> every LDG is one 128B line). Vertical 7-window sums of
//            {x,y,xx,yy,xy} via register sliding over 22 fully-unrolled row
//            loads (MLP ~44/thread). Results staged in 5 SMEM planes with odd
//            stride 65 (conflict-free row-strided reads in phase 2).
//   Phase 2: horizontal 7-window sliding over SMEM column sums, SSIM math,
//            block reduce, one atomicAdd(double) per block.

#define WIN      7
#define IMG      320
#define OUT      314                 // 320 - 7 + 1
#define NIMG     256                 // 32 * 8
#define NELEM    25240576.0          // 256 * 314 * 314

#define COLS     64                  // input columns per block
#define TILE_W   58                  // output columns per block (COLS - 6)
#define TILE_H   32                  // output rows per block
#define SEG_ROWS 16                  // output rows per thread-segment
#define IN_ROWS  22                  // SEG_ROWS + 6 input rows loaded
#define SSTRIDE  (COLS + 1)          // 65: odd word stride -> conflict-free

__device__ double g_accum;

__global__ void ssim_init_kernel() { g_accum = 0.0; }

__global__ void ssim_final_kernel(float* out) {
    out[0] = (float)(1.0 - g_accum / NELEM);
}

__global__ __launch_bounds__(128) void ssim_main_kernel(
    const float* __restrict__ X, const float* __restrict__ Y,
    const float* __restrict__ data_range, const float* __restrict__ w)
{
    __shared__ float s_sx [TILE_H][SSTRIDE];
    __shared__ float s_sy [TILE_H][SSTRIDE];
    __shared__ float s_sxx[TILE_H][SSTRIDE];
    __shared__ float s_syy[TILE_H][SSTRIDE];
    __shared__ float s_sxy[TILE_H][SSTRIDE];
    __shared__ float warpsum[4];

    const int img = blockIdx.z;
    const int tx0 = blockIdx.x * TILE_W;
    const int ty0 = blockIdx.y * TILE_H;
    const float* Xb = X + (size_t)img * IMG * IMG;
    const float* Yb = Y + (size_t)img * IMG * IMG;
    const int tid = threadIdx.x;

    // ---------------- Phase 1: vertical window sums (coalesced) ------------
    {
        const int col = tid & (COLS - 1);       // 0..63, lane-contiguous
        const int seg = tid >> 6;               // 0..1
        const int gx  = tx0 + col;
        const int gy0 = ty0 + seg * SEG_ROWS;
        const bool colok = (gx < IMG);
        const float* xp = Xb + (size_t)gy0 * IMG + gx;
        const float* yp = Yb + (size_t)gy0 * IMG + gx;

        float xv[IN_ROWS], yv[IN_ROWS];
        #pragma unroll
        for (int j = 0; j < IN_ROWS; j++) {
            const bool ok = colok && (gy0 + j < IMG);
            xv[j] = ok ? __ldg(xp + (size_t)j * IMG) : 0.0f;
            yv[j] = ok ? __ldg(yp + (size_t)j * IMG) : 0.0f;
        }

        float sx = 0.f, sy = 0.f, sxx = 0.f, syy = 0.f, sxy = 0.f;
        #pragma unroll
        for (int k = 0; k < WIN; k++) {
            sx += xv[k];
            sy += yv[k];
            sxx = fmaf(xv[k], xv[k], sxx);
            syy = fmaf(yv[k], yv[k], syy);
            sxy = fmaf(xv[k], yv[k], sxy);
        }
        const int rbase = seg * SEG_ROWS;
        s_sx [rbase][col] = sx;  s_sy [rbase][col] = sy;
        s_sxx[rbase][col] = sxx; s_syy[rbase][col] = syy;
        s_sxy[rbase][col] = sxy;

        #pragma unroll
        for (int r = 1; r < SEG_ROWS; r++) {
            const float xn = xv[r + 6], yn = yv[r + 6];
            const float xo = xv[r - 1], yo = yv[r - 1];
            sx += xn - xo;
            sy += yn - yo;
            sxx = fmaf(xn, xn, fmaf(-xo, xo, sxx));
            syy = fmaf(yn, yn, fmaf(-yo, yo, syy));
            sxy = fmaf(xn, yn, fmaf(-xo, yo, sxy));
            s_sx [rbase + r][col] = sx;  s_sy [rbase + r][col] = sy;
            s_sxx[rbase + r][col] = sxx; s_syy[rbase + r][col] = syy;
            s_sxy[rbase + r][col] = sxy;
        }
    }
    __syncthreads();

    // ---------------- Phase 2: horizontal sliding + SSIM -------------------
    const float wscale = w[0];                  // 1/49 (uniform box weight)
    const float dr  = data_range[0];
    const float c1t = 0.01f * dr;
    const float c2t = 0.03f * dr;
    const float C1  = c1t * c1t;
    const float C2  = c2t * c2t;
    const float COV = 49.0f / 48.0f;

    float local = 0.f;
    {
        const int r  = tid & (TILE_H - 1);      // output row in tile
        const int q  = tid >> 5;                // 0..3 column quarter
        const int c0 = q * 15;
        const int cend = (q == 3) ? TILE_W : (c0 + 15);
        const int oy = ty0 + r;

        if (oy < OUT) {
            float sx = 0.f, sy = 0.f, sxx = 0.f, syy = 0.f, sxy = 0.f;
            #pragma unroll
            for (int k = 0; k < WIN; k++) {
                sx  += s_sx [r][c0 + k];
                sy  += s_sy [r][c0 + k];
                sxx += s_sxx[r][c0 + k];
                syy += s_syy[r][c0 + k];
                sxy += s_sxy[r][c0 + k];
            }
            for (int c = c0; c < cend; c++) {
                if (tx0 + c < OUT) {
                    const float ux  = sx  * wscale;
                    const float uy  = sy  * wscale;
                    const float uxx = sxx * wscale;
                    const float uyy = syy * wscale;
                    const float uxy = sxy * wscale;
                    const float vx  = COV * (uxx - ux * ux);
                    const float vy  = COV * (uyy - uy * uy);
                    const float vxy = COV * (uxy - ux * uy);
                    const float A1 = 2.0f * ux * uy + C1;
                    const float A2 = 2.0f * vxy + C2;
                    const float B1 = ux * ux + uy * uy + C1;
                    const float B2 = vx + vy + C2;
                    local += __fdividef(A1 * A2, B1 * B2 + 1e-8f);
                }
                if (c + 1 < cend) {
                    sx  += s_sx [r][c + 7] - s_sx [r][c];
                    sy  += s_sy [r][c + 7] - s_sy [r][c];
                    sxx += s_sxx[r][c + 7] - s_sxx[r][c];
                    syy += s_syy[r][c + 7] - s_syy[r][c];
                    sxy += s_sxy[r][c + 7] - s_sxy[r][c];
                }
            }
        }
    }

    // ---------------- Block reduction --------------------------------------
    #pragma unroll
    for (int off = 16; off > 0; off >>= 1)
        local += __shfl_down_sync(0xffffffffu, local, off);
    if ((tid & 31) == 0) warpsum[tid >> 5] = local;
    __syncthreads();
    if (tid == 0) {
        const float v = warpsum[0] + warpsum[1] + warpsum[2] + warpsum[3];
        atomicAdd(&g_accum, (double)v);
    }
}

extern "C" void kernel_launch(void* const* d_in, const int* in_sizes, int n_in,
                              void* d_out, int out_size) {
    const float* X  = (const float*)d_in[0];
    const float* Y  = (const float*)d_in[1];
    const float* dr = (const float*)d_in[2];
    const float* w  = (const float*)d_in[3];
    float* out = (float*)d_out;

    ssim_init_kernel<<<1, 1>>>();
    dim3 grid((OUT + TILE_W - 1) / TILE_W,   // 6
              (OUT + TILE_H - 1) / TILE_H,   // 10
              NIMG);                         // 256
    ssim_main_kernel<<<grid, 128>>>(X, Y, dr, w);
    ssim_final_kernel<<<1, 1>>>(out);
}

// round 5
// speedup vs baseline: 1.9257x; 1.1258x over previous
#include <cuda_runtime.h>
#include <cuda_bf16.h>

// SSIM loss: X,Y (32,8,320,320) fp32, 7x7 uniform box (valid), out = 1 - mean(S)
//
// Vertical-first separable box sums (coalesced LDG), f32x2 packed math,
// float2 SMEM planes, register-ring horizontal slide, fused finalize.

#define WIN      7
#define IMG      320
#define OUT      314
#define NIMG     256
#define NELEM    25240576.0

#define COLS     64
#define TILE_W   58
#define TILE_H   32
#define SEG_ROWS 16
#define IN_ROWS  22
#define SSTRIDE  (COLS + 1)          // 65 float2 / float entries per row
#define GRID_X   6
#define GRID_Y   10
#define NBLOCKS  (GRID_X * GRID_Y * NIMG)   // 15360

__device__ double g_accum;
__device__ unsigned int g_count;

// ---- packed f32x2 helpers (sm_103a) ----
__device__ __forceinline__ float2 f2add(float2 a, float2 b) {
    unsigned long long ra = *(unsigned long long*)&a;
    unsigned long long rb = *(unsigned long long*)&b;
    unsigned long long rd;
    asm("add.rn.f32x2 %0, %1, %2;" : "=l"(rd) : "l"(ra), "l"(rb));
    return *(float2*)&rd;
}
__device__ __forceinline__ float2 f2mul(float2 a, float2 b) {
    unsigned long long ra = *(unsigned long long*)&a;
    unsigned long long rb = *(unsigned long long*)&b;
    unsigned long long rd;
    asm("mul.rn.f32x2 %0, %1, %2;" : "=l"(rd) : "l"(ra), "l"(rb));
    return *(float2*)&rd;
}
__device__ __forceinline__ float2 f2fma(float2 a, float2 b, float2 c) {
    unsigned long long ra = *(unsigned long long*)&a;
    unsigned long long rb = *(unsigned long long*)&b;
    unsigned long long rc = *(unsigned long long*)&c;
    unsigned long long rd;
    asm("fma.rn.f32x2 %0, %1, %2, %3;" : "=l"(rd) : "l"(ra), "l"(rb), "l"(rc));
    return *(float2*)&rd;
}

__global__ __launch_bounds__(128) void ssim_main_kernel(
    const float* __restrict__ X, const float* __restrict__ Y,
    const float* __restrict__ data_range, const float* __restrict__ w,
    float* __restrict__ out)
{
    __shared__ float2 s_P[TILE_H][SSTRIDE];   // (sum_x, sum_y)
    __shared__ float2 s_Q[TILE_H][SSTRIDE];   // (sum_xx, sum_yy)
    __shared__ float  s_R[TILE_H][SSTRIDE];   // sum_xy
    __shared__ float  warpsum[4];

    const int img = blockIdx.z;
    const int tx0 = blockIdx.x * TILE_W;
    const int ty0 = blockIdx.y * TILE_H;
    const float* Xb = X + (size_t)img * IMG * IMG;
    const float* Yb = Y + (size_t)img * IMG * IMG;
    const int tid = threadIdx.x;
    const float2 neg1 = make_float2(-1.f, -1.f);

    // ---------------- Phase 1: vertical window sums (coalesced) ------------
    {
        const int col = tid & (COLS - 1);
        const int seg = tid >> 6;
        const int gx  = tx0 + col;
        const int gy0 = ty0 + seg * SEG_ROWS;
        const bool colok = (gx < IMG);
        const float* xp = Xb + (size_t)gy0 * IMG + gx;
        const float* yp = Yb + (size_t)gy0 * IMG + gx;

        float xv[IN_ROWS], yv[IN_ROWS];
        #pragma unroll
        for (int j = 0; j < IN_ROWS; j++) {
            const bool ok = colok && (gy0 + j < IMG);
            xv[j] = ok ? __ldg(xp + (size_t)j * IMG) : 0.0f;
            yv[j] = ok ? __ldg(yp + (size_t)j * IMG) : 0.0f;
        }

        float2 P = make_float2(0.f, 0.f);
        float2 Q = make_float2(0.f, 0.f);
        float  R = 0.f;
        #pragma unroll
        for (int k = 0; k < WIN; k++) {
            const float2 p = make_float2(xv[k], yv[k]);
            P = f2add(P, p);
            Q = f2fma(p, p, Q);
            R = fmaf(xv[k], yv[k], R);
        }
        const int rbase = seg * SEG_ROWS;
        s_P[rbase][col] = P; s_Q[rbase][col] = Q; s_R[rbase][col] = R;

        #pragma unroll
        for (int r = 1; r < SEG_ROWS; r++) {
            const float2 pn = make_float2(xv[r + 6], yv[r + 6]);
            const float2 po = make_float2(xv[r - 1], yv[r - 1]);
            P = f2add(P, pn);
            P = f2fma(po, neg1, P);
            Q = f2fma(pn, pn, Q);
            const float2 mpo = f2mul(po, neg1);
            Q = f2fma(mpo, po, Q);
            R = fmaf(pn.x, pn.y, R);
            R = fmaf(-po.x, po.y, R);
            s_P[rbase + r][col] = P;
            s_Q[rbase + r][col] = Q;
            s_R[rbase + r][col] = R;
        }
    }
    __syncthreads();

    // ---------------- Phase 2: horizontal sliding + SSIM -------------------
    // Rescaled algebra (everything * (1/w)^2): eliminates per-pixel wscale.
    const float w0  = w[0];
    const float iw  = 1.0f / w0;                // ~49
    const float dr  = data_range[0];
    const float c1t = 0.01f * dr;
    const float c2t = 0.03f * dr;
    const float C1s = (c1t * c1t) * iw * iw;
    const float C2s = (c2t * c2t) * iw * iw;
    const float COV  = 49.0f / 48.0f;
    const float COV2 = 2.0f * COV;
    const float epsS = 1e-8f * (iw * iw) * (iw * iw);
    const float2 iw2 = make_float2(iw, iw);

    float local = 0.f;
    {
        const int r  = tid & (TILE_H - 1);
        const int q  = tid >> 5;
        const int c0 = q * 15;
        const bool rowok = (ty0 + r < OUT);

        float2 rP[7], rQ[7];
        float  rR[7];
        float2 P = make_float2(0.f, 0.f);
        float2 Q = make_float2(0.f, 0.f);
        float  R = 0.f;
        #pragma unroll
        for (int k = 0; k < WIN; k++) {
            rP[k] = s_P[r][c0 + k];
            rQ[k] = s_Q[r][c0 + k];
            rR[k] = s_R[r][c0 + k];
            P = f2add(P, rP[k]);
            Q = f2add(Q, rQ[k]);
            R += rR[k];
        }

        #pragma unroll
        for (int ci = 0; ci < 15; ci++) {
            const int c = c0 + ci;
            const bool active = rowok && (c < TILE_W) && (tx0 + c < OUT);

            const float sx = P.x, sy = P.y;
            const float2 PP = f2mul(P, P);            // (sx^2, sy^2)
            const float t1 = sx * sy;
            const float A1 = fmaf(t1, 2.0f, C1s);
            const float B1 = PP.x + PP.y + C1s;
            const float2 nPP = f2mul(PP, neg1);
            const float2 qv = f2fma(Q, iw2, nPP);     // (iw*sxx - sx^2, ...)
            const float inner = fmaf(iw, R, -t1);
            const float A2 = fmaf(COV2, inner, C2s);
            const float B2 = fmaf(COV, qv.x + qv.y, C2s);
            const float num = A1 * A2;
            const float den = fmaf(B1, B2, epsS);
            if (active) local += __fdividef(num, den);

            if (ci < 14 && c + 7 < COLS) {
                const int slot = ci % 7;
                const float2 nPn = s_P[r][c + 7];
                const float2 nQn = s_Q[r][c + 7];
                const float  nRn = s_R[r][c + 7];
                P = f2add(P, nPn);
                P = f2fma(rP[slot], neg1, P);
                Q = f2add(Q, nQn);
                Q = f2fma(rQ[slot], neg1, Q);
                R += nRn - rR[slot];
                rP[slot] = nPn; rQ[slot] = nQn; rR[slot] = nRn;
            }
        }
    }

    // ---------------- Block reduction + fused finalize ----------------------
    #pragma unroll
    for (int off = 16; off > 0; off >>= 1)
        local += __shfl_down_sync(0xffffffffu, local, off);
    if ((tid & 31) == 0) warpsum[tid >> 5] = local;
    __syncthreads();
    if (tid == 0) {
        const float v = warpsum[0] + warpsum[1] + warpsum[2] + warpsum[3];
        atomicAdd(&g_accum, (double)v);
        __threadfence();
        const unsigned done = atomicAdd(&g_count, 1u);
        if (done == NBLOCKS - 1) {
            const double total = atomicAdd(&g_accum, 0.0);
            out[0] = (float)(1.0 - total / NELEM);
            g_accum = 0.0;            // reset for next graph replay
            g_count = 0u;
        }
    }
}

extern "C" void kernel_launch(void* const* d_in, const int* in_sizes, int n_in,
                              void* d_out, int out_size) {
    const float* X  = (const float*)d_in[0];
    const float* Y  = (const float*)d_in[1];
    const float* dr = (const float*)d_in[2];
    const float* w  = (const float*)d_in[3];
    float* out = (float*)d_out;

    dim3 grid(GRID_X, GRID_Y, NIMG);
    ssim_main_kernel<<<grid, 128>>>(X, Y, dr, w, out);
}

// round 6
// speedup vs baseline: 2.3963x; 1.2444x over previous
#include <cuda_runtime.h>
#include <cuda_bf16.h>

// SSIM loss: X,Y (32,8,320,320) fp32, 7x7 uniform box (valid), out = 1 - mean(S)
//
// Vertical-first separable box sums. Key changes this round:
//  - 4 staged quantities (sx, sy, sxx+syy, sxy) in ONE float4 SMEM plane
//    (uxx/uyy only ever appear summed in B2) -> 20% less SMEM/LDS/STS.
//  - TILE_H=16, smem 16.7KB, __launch_bounds__(128,8) -> ~50% occupancy.
//  - Phase-2: chunk of 8 outputs, 7-deep float4 register ring, LDS.128 only.

#define WIN      7
#define IMG      320
#define OUT      314
#define NIMG     256
#define NELEM    25240576.0

#define COLS     64
#define TILE_W   58
#define TILE_H   16
#define SEG_ROWS 8                   // output rows per thread-segment
#define IN_ROWS  14                  // SEG_ROWS + 6
#define SSTRIDE  (COLS + 1)          // 65 float4 entries per row
#define GRID_X   6
#define GRID_Y   20
#define NBLOCKS  (GRID_X * GRID_Y * NIMG)   // 30720

__device__ double g_accum;
__device__ unsigned int g_count;

// ---- packed f32x2 helpers (sm_103a) ----
__device__ __forceinline__ float2 f2add(float2 a, float2 b) {
    unsigned long long ra = *(unsigned long long*)&a;
    unsigned long long rb = *(unsigned long long*)&b;
    unsigned long long rd;
    asm("add.rn.f32x2 %0, %1, %2;" : "=l"(rd) : "l"(ra), "l"(rb));
    return *(float2*)&rd;
}
__device__ __forceinline__ float2 f2mul(float2 a, float2 b) {
    unsigned long long ra = *(unsigned long long*)&a;
    unsigned long long rb = *(unsigned long long*)&b;
    unsigned long long rd;
    asm("mul.rn.f32x2 %0, %1, %2;" : "=l"(rd) : "l"(ra), "l"(rb));
    return *(float2*)&rd;
}
__device__ __forceinline__ float2 f2fma(float2 a, float2 b, float2 c) {
    unsigned long long ra = *(unsigned long long*)&a;
    unsigned long long rb = *(unsigned long long*)&b;
    unsigned long long rc = *(unsigned long long*)&c;
    unsigned long long rd;
    asm("fma.rn.f32x2 %0, %1, %2, %3;" : "=l"(rd) : "l"(ra), "l"(rb), "l"(rc));
    return *(float2*)&rd;
}

__global__ __launch_bounds__(128, 8) void ssim_main_kernel(
    const float* __restrict__ X, const float* __restrict__ Y,
    const float* __restrict__ data_range, const float* __restrict__ w,
    float* __restrict__ out)
{
    __shared__ float4 s_E[TILE_H][SSTRIDE];   // (sx, sy, sxx+syy, sxy)
    __shared__ float  warpsum[4];

    const int img = blockIdx.z;
    const int tx0 = blockIdx.x * TILE_W;
    const int ty0 = blockIdx.y * TILE_H;
    const float* Xb = X + (size_t)img * IMG * IMG;
    const float* Yb = Y + (size_t)img * IMG * IMG;
    const int tid = threadIdx.x;
    const float2 neg1 = make_float2(-1.f, -1.f);

    // ---------------- Phase 1: vertical window sums (coalesced) ------------
    {
        const int col = tid & (COLS - 1);       // lane-contiguous columns
        const int seg = tid >> 6;               // 0..1, 8 output rows each
        const int gx  = tx0 + col;
        const int gy0 = ty0 + seg * SEG_ROWS;
        const bool colok = (gx < IMG);
        const float* xp = Xb + (size_t)gy0 * IMG + gx;
        const float* yp = Yb + (size_t)gy0 * IMG + gx;

        float xv[IN_ROWS], yv[IN_ROWS];
        #pragma unroll
        for (int j = 0; j < IN_ROWS; j++) {
            const bool ok = colok && (gy0 + j < IMG);
            xv[j] = ok ? __ldg(xp + (size_t)j * IMG) : 0.0f;
            yv[j] = ok ? __ldg(yp + (size_t)j * IMG) : 0.0f;
        }

        float2 P = make_float2(0.f, 0.f);       // (sx, sy)
        float2 Q = make_float2(0.f, 0.f);       // (sxx, syy) -> summed at store
        float  R = 0.f;                         // sxy
        #pragma unroll
        for (int k = 0; k < WIN; k++) {
            const float2 p = make_float2(xv[k], yv[k]);
            P = f2add(P, p);
            Q = f2fma(p, p, Q);
            R = fmaf(xv[k], yv[k], R);
        }
        const int rbase = seg * SEG_ROWS;
        s_E[rbase][col] = make_float4(P.x, P.y, Q.x + Q.y, R);

        #pragma unroll
        for (int r = 1; r < SEG_ROWS; r++) {
            const float2 pn = make_float2(xv[r + 6], yv[r + 6]);
            const float2 po = make_float2(xv[r - 1], yv[r - 1]);
            P = f2add(P, pn);
            P = f2fma(po, neg1, P);
            Q = f2fma(pn, pn, Q);
            const float2 mpo = f2mul(po, neg1);
            Q = f2fma(mpo, po, Q);
            R = fmaf(pn.x, pn.y, R);
            R = fmaf(-po.x, po.y, R);
            s_E[rbase + r][col] = make_float4(P.x, P.y, Q.x + Q.y, R);
        }
    }
    __syncthreads();

    // ---------------- Phase 2: horizontal sliding + SSIM -------------------
    // Rescaled algebra (everything * (1/w)^2): no per-pixel wscale mults.
    const float w0  = w[0];
    const float iw  = 1.0f / w0;                // ~49
    const float dr  = data_range[0];
    const float c1t = 0.01f * dr;
    const float c2t = 0.03f * dr;
    const float C1s = (c1t * c1t) * iw * iw;
    const float C2s = (c2t * c2t) * iw * iw;
    const float COV  = 49.0f / 48.0f;
    const float COV2 = 2.0f * COV;
    const float epsS = 1e-8f * (iw * iw) * (iw * iw);

    float local = 0.f;
    {
        const int r  = tid & (TILE_H - 1);      // output row in tile
        const int q  = tid >> 4;                // 0..7 column chunk
        const int c0 = q * 8;
        const bool rowok = (ty0 + r < OUT);

        float4 ring[7];
        float2 Sp = make_float2(0.f, 0.f);      // (sx, sy)
        float2 Sq = make_float2(0.f, 0.f);      // (sqq, sxy)
        #pragma unroll
        for (int k = 0; k < WIN; k++) {
            const float4 e = s_E[r][c0 + k];
            ring[k] = e;
            Sp = f2add(Sp, make_float2(e.x, e.y));
            Sq = f2add(Sq, make_float2(e.z, e.w));
        }

        #pragma unroll
        for (int ci = 0; ci < 8; ci++) {
            const int c = c0 + ci;
            const bool active = rowok && (c < TILE_W) && (tx0 + c < OUT);

            const float sx = Sp.x, sy = Sp.y;
            const float sqq = Sq.x, sxy = Sq.y;
            const float2 PP = f2mul(Sp, Sp);          // (sx^2, sy^2)
            const float t1 = sx * sy;
            const float b1 = PP.x + PP.y;
            const float A1 = fmaf(t1, 2.0f, C1s);
            const float B1 = b1 + C1s;
            const float A2 = fmaf(COV2, fmaf(iw, sxy, -t1), C2s);
            const float B2 = fmaf(COV,  fmaf(iw, sqq, -b1), C2s);
            const float num = A1 * A2;
            const float den = fmaf(B1, B2, epsS);
            if (active) local += __fdividef(num, den);

            if (ci < 7 && c + 7 < COLS) {
                const float4 ne = s_E[r][c + 7];
                const float4 oe = ring[ci];
                Sp = f2add(Sp, make_float2(ne.x, ne.y));
                Sp = f2fma(make_float2(oe.x, oe.y), neg1, Sp);
                Sq = f2add(Sq, make_float2(ne.z, ne.w));
                Sq = f2fma(make_float2(oe.z, oe.w), neg1, Sq);
            }
        }
    }

    // ---------------- Block reduction + fused finalize ----------------------
    #pragma unroll
    for (int off = 16; off > 0; off >>= 1)
        local += __shfl_down_sync(0xffffffffu, local, off);
    if ((tid & 31) == 0) warpsum[tid >> 5] = local;
    __syncthreads();
    if (tid == 0) {
        const float v = warpsum[0] + warpsum[1] + warpsum[2] + warpsum[3];
        atomicAdd(&g_accum, (double)v);
        __threadfence();
        const unsigned done = atomicAdd(&g_count, 1u);
        if (done == NBLOCKS - 1) {
            const double total = atomicAdd(&g_accum, 0.0);
            out[0] = (float)(1.0 - total / NELEM);
            g_accum = 0.0;            // reset for next graph replay
            g_count = 0u;
        }
    }
}

extern "C" void kernel_launch(void* const* d_in, const int* in_sizes, int n_in,
                              void* d_out, int out_size) {
    const float* X  = (const float*)d_in[0];
    const float* Y  = (const float*)d_in[1];
    const float* dr = (const float*)d_in[2];
    const float* w  = (const float*)d_in[3];
    float* out = (float*)d_out;

    dim3 grid(GRID_X, GRID_Y, NIMG);
    ssim_main_kernel<<<grid, 128>>>(X, Y, dr, w, out);
}